// round 1
// baseline (speedup 1.0000x reference)
#include <cuda_runtime.h>
#include <cuda_bf16.h>

// Problem constants
#define HH 256
#define WW 256
#define ICH 16
#define OCH 128          // NP*LP = 8*16
#define NIMG 16          // B*NC = 4*4
#define TILE 16
#define OCC 64           // oc chunk per conv block
#define HALO 20          // TILE + 4 (kernel 5, pad 2)

// Scratch: votes in NHWC layout  ((n*H + h)*W + w)*128 + oc, oc = np*16+lp
__device__ float g_votes[(size_t)NIMG * HH * WW * OCH];   // 512 MB

// ---------------------------------------------------------------------------
// Conv kernel: 5x5, pad 2, fp32. Block = 256 thr, computes 16x16 px x 64 oc.
// Smem: input halo 16ch x 20x20 (25.6KB) + weights transposed [400][64] (102.4KB)
// Thread: 4 px (contig in w) x 16 oc accumulators.
// ---------------------------------------------------------------------------
__global__ __launch_bounds__(256, 1)
void conv_votes_kernel(const float* __restrict__ x, const float* __restrict__ Wg) {
    extern __shared__ float smem[];
    float* xs = smem;                         // [16][20][20] = 6400 floats
    float* ws = smem + ICH * HALO * HALO;     // [400][64]    = 25600 floats

    const int t = threadIdx.x;
    const int bidx = blockIdx.x;
    const int bx  = bidx & 15;
    const int by  = (bidx >> 4) & 15;
    const int n   = (bidx >> 8) & 15;
    const int ocb = (bidx >> 12) * OCC;       // 0 or 64

    // Load + transpose weights: Wg[oc][ic][ky][kx] -> ws[ic*25+tap][oc_local]
    for (int i = t; i < OCC * 400; i += 256) {
        int oc_l = i / 400;
        int k = i - oc_l * 400;
        ws[k * OCC + oc_l] = Wg[(size_t)(ocb + oc_l) * 400 + k];
    }

    // Load input halo with zero padding
    const int h0 = by * TILE - 2, w0 = bx * TILE - 2;
    const float* xn = x + (size_t)n * ICH * HH * WW;
    for (int i = t; i < ICH * HALO * HALO; i += 256) {
        int ic = i / (HALO * HALO);
        int rem = i - ic * (HALO * HALO);
        int r = rem / HALO;
        int c = rem - r * HALO;
        int hh = h0 + r, ww = w0 + c;
        float v = 0.f;
        if (hh >= 0 && hh < HH && ww >= 0 && ww < WW)
            v = xn[(size_t)ic * HH * WW + hh * WW + ww];
        xs[i] = v;
    }
    __syncthreads();

    const int ocg = t & 3;            // 16-oc group within chunk
    const int pg  = t >> 2;           // 0..63 pixel group
    const int py  = pg >> 2;          // 0..15
    const int px  = (pg & 3) << 2;    // 0,4,8,12

    float acc[4][16];
#pragma unroll
    for (int p = 0; p < 4; p++)
#pragma unroll
        for (int o = 0; o < 16; o++) acc[p][o] = 0.f;

#pragma unroll 1
    for (int ic = 0; ic < ICH; ic++) {
#pragma unroll 1
        for (int ky = 0; ky < 5; ky++) {
            const float4* rp = (const float4*)&xs[ic * 400 + (py + ky) * HALO + px];
            float4 a0 = rp[0], a1 = rp[1];
            float in[8] = {a0.x, a0.y, a0.z, a0.w, a1.x, a1.y, a1.z, a1.w};
#pragma unroll
            for (int kx = 0; kx < 5; kx++) {
                const float4* wp =
                    (const float4*)&ws[(ic * 25 + ky * 5 + kx) * OCC + (ocg << 4)];
                float4 q0 = wp[0], q1 = wp[1], q2 = wp[2], q3 = wp[3];
                float wv[16] = {q0.x, q0.y, q0.z, q0.w, q1.x, q1.y, q1.z, q1.w,
                                q2.x, q2.y, q2.z, q2.w, q3.x, q3.y, q3.z, q3.w};
#pragma unroll
                for (int p = 0; p < 4; p++)
#pragma unroll
                    for (int o = 0; o < 16; o++)
                        acc[p][o] += in[p + kx] * wv[o];
            }
        }
    }

    // Store NHWC
    const int h = by * TILE + py;
#pragma unroll
    for (int p = 0; p < 4; p++) {
        int w = bx * TILE + px + p;
        float4* o4 = (float4*)&g_votes[(((size_t)n * HH + h) * WW + w) * OCH
                                       + ocb + (ocg << 4)];
        o4[0] = make_float4(acc[p][0],  acc[p][1],  acc[p][2],  acc[p][3]);
        o4[1] = make_float4(acc[p][4],  acc[p][5],  acc[p][6],  acc[p][7]);
        o4[2] = make_float4(acc[p][8],  acc[p][9],  acc[p][10], acc[p][11]);
        o4[3] = make_float4(acc[p][12], acc[p][13], acc[p][14], acc[p][15]);
    }
}

// ---------------------------------------------------------------------------
// Routing kernel: one warp per pixel. lane = nc*8+np, v[16] over lp in regs.
// 3 iterations: softmax over NP (shfl 1,2,4), sum over NC (shfl 8,16),
// squash over LP (lane-local), sims += <v, parent>.
// Block = 8 warps = 8 consecutive pixels; output transposed via smem so the
// (B,NP,LP,H,W)-layout store is sector-coalesced.
// ---------------------------------------------------------------------------
__global__ __launch_bounds__(256)
void routing_kernel(float* __restrict__ out) {
    __shared__ float out_s[128][8];

    const int warp = threadIdx.x >> 5;
    const int lane = threadIdx.x & 31;
    const int pixBase = blockIdx.x << 3;          // over B*H*W = 262144, same b per block
    const int pix = pixBase + warp;
    const int b  = pix >> 16;                     // H*W = 65536
    const int hw = pix & 65535;
    const int nc = lane >> 3;
    const int np = lane & 7;

    const float4* vp = (const float4*)
        &g_votes[(((size_t)(b * 4 + nc) << 16) + hw) * OCH + (np << 4)];
    float4 v0 = vp[0], v1 = vp[1], v2 = vp[2], v3 = vp[3];
    float v[16] = {v0.x, v0.y, v0.z, v0.w, v1.x, v1.y, v1.z, v1.w,
                   v2.x, v2.y, v2.z, v2.w, v3.x, v3.y, v3.z, v3.w};

    float sims = 0.f;
    float parent[16];

#pragma unroll
    for (int it = 0; it < 3; it++) {
        // softmax over np (8 lanes sharing nc)
        float m = sims;
        m = fmaxf(m, __shfl_xor_sync(0xffffffffu, m, 1));
        m = fmaxf(m, __shfl_xor_sync(0xffffffffu, m, 2));
        m = fmaxf(m, __shfl_xor_sync(0xffffffffu, m, 4));
        float e = __expf(sims - m);
        float s = e;
        s += __shfl_xor_sync(0xffffffffu, s, 1);
        s += __shfl_xor_sync(0xffffffffu, s, 2);
        s += __shfl_xor_sync(0xffffffffu, s, 4);
        float c = e / s;

        // parent_bs = sum over nc of c*v ; replicated across the 4 nc-lanes
        float sq = 0.f;
#pragma unroll
        for (int l = 0; l < 16; l++) {
            float p = c * v[l];
            p += __shfl_xor_sync(0xffffffffu, p, 8);
            p += __shfl_xor_sync(0xffffffffu, p, 16);
            parent[l] = p;
            sq += p * p;
        }
        // squash over lp
        float norm  = sqrtf(sq);
        float scale = norm / (1.f + sq + 1e-4f);
        float dot = 0.f;
#pragma unroll
        for (int l = 0; l < 16; l++) {
            parent[l] *= scale;
            dot += v[l] * parent[l];
        }
        sims += dot;
    }

    if (nc == 0) {
#pragma unroll
        for (int l = 0; l < 16; l++)
            out_s[(np << 4) + l][warp] = parent[l];
    }
    __syncthreads();

    // Coalesced store: thread t writes 4 floats of channel c at 4 consecutive px
    const int c    = threadIdx.x >> 1;
    const int half = threadIdx.x & 1;
    const int bb   = pixBase >> 16;
    const int hw0  = pixBase & 65535;
    float4 val = make_float4(out_s[c][half * 4 + 0], out_s[c][half * 4 + 1],
                             out_s[c][half * 4 + 2], out_s[c][half * 4 + 3]);
    float4* op = (float4*)&out[((size_t)bb * 128 + c) * 65536 + hw0 + half * 4];
    *op = val;
}

// ---------------------------------------------------------------------------
extern "C" void kernel_launch(void* const* d_in, const int* in_sizes, int n_in,
                              void* d_out, int out_size) {
    const float* x  = (const float*)d_in[0];   // (4,4,16,256,256)
    const float* Wg = (const float*)d_in[1];   // (128,16,5,5)
    float* out = (float*)d_out;                // (4,8,16,256,256)

    const int smem_bytes = (ICH * HALO * HALO + 400 * OCC) * (int)sizeof(float); // 128000
    cudaFuncSetAttribute(conv_votes_kernel,
                         cudaFuncAttributeMaxDynamicSharedMemorySize, smem_bytes);

    conv_votes_kernel<<<16 * 16 * 16 * 2, 256, smem_bytes>>>(x, Wg);
    routing_kernel<<<(4 * 256 * 256) / 8, 256>>>(out);
}

// round 2
// speedup vs baseline: 1.0019x; 1.0019x over previous
#include <cuda_runtime.h>
#include <cuda_bf16.h>

// Problem constants
#define HH 256
#define WW 256
#define ICH 16
#define OCH 128          // NP*LP = 8*16
#define NIMG 16          // B*NC = 4*4
#define TILE 16
#define OCC 64           // oc chunk per conv block
#define HALO 20          // TILE + 4 (kernel 5, pad 2)

// Scratch: votes in NHWC layout  ((n*H + h)*W + w)*128 + oc, oc = np*16+lp
__device__ float g_votes[(size_t)NIMG * HH * WW * OCH];   // 512 MB

// ---------------------------------------------------------------------------
// Conv kernel: 5x5, pad 2, fp32. Block = 256 thr, computes 16x16 px x 64 oc.
// Smem: input halo 16ch x 20x20 (25.6KB) + weights transposed [400][64] (102.4KB)
// Thread: 4 px (contig in w) x 16 oc accumulators.
// ---------------------------------------------------------------------------
__global__ __launch_bounds__(256, 1)
void conv_votes_kernel(const float* __restrict__ x, const float* __restrict__ Wg) {
    extern __shared__ float smem[];
    float* xs = smem;                         // [16][20][20] = 6400 floats
    float* ws = smem + ICH * HALO * HALO;     // [400][64]    = 25600 floats

    const int t = threadIdx.x;
    const int bidx = blockIdx.x;
    const int bx  = bidx & 15;
    const int by  = (bidx >> 4) & 15;
    const int n   = (bidx >> 8) & 15;
    const int ocb = (bidx >> 12) * OCC;       // 0 or 64

    // Load + transpose weights: Wg[oc][ic][ky][kx] -> ws[ic*25+tap][oc_local]
    for (int i = t; i < OCC * 400; i += 256) {
        int oc_l = i / 400;
        int k = i - oc_l * 400;
        ws[k * OCC + oc_l] = Wg[(size_t)(ocb + oc_l) * 400 + k];
    }

    // Load input halo with zero padding
    const int h0 = by * TILE - 2, w0 = bx * TILE - 2;
    const float* xn = x + (size_t)n * ICH * HH * WW;
    for (int i = t; i < ICH * HALO * HALO; i += 256) {
        int ic = i / (HALO * HALO);
        int rem = i - ic * (HALO * HALO);
        int r = rem / HALO;
        int c = rem - r * HALO;
        int hh = h0 + r, ww = w0 + c;
        float v = 0.f;
        if (hh >= 0 && hh < HH && ww >= 0 && ww < WW)
            v = xn[(size_t)ic * HH * WW + hh * WW + ww];
        xs[i] = v;
    }
    __syncthreads();

    const int ocg = t & 3;            // 16-oc group within chunk
    const int pg  = t >> 2;           // 0..63 pixel group
    const int py  = pg >> 2;          // 0..15
    const int px  = (pg & 3) << 2;    // 0,4,8,12

    float acc[4][16];
#pragma unroll
    for (int p = 0; p < 4; p++)
#pragma unroll
        for (int o = 0; o < 16; o++) acc[p][o] = 0.f;

#pragma unroll 1
    for (int ic = 0; ic < ICH; ic++) {
#pragma unroll 1
        for (int ky = 0; ky < 5; ky++) {
            const float4* rp = (const float4*)&xs[ic * 400 + (py + ky) * HALO + px];
            float4 a0 = rp[0], a1 = rp[1];
            float in[8] = {a0.x, a0.y, a0.z, a0.w, a1.x, a1.y, a1.z, a1.w};
#pragma unroll
            for (int kx = 0; kx < 5; kx++) {
                const float4* wp =
                    (const float4*)&ws[(ic * 25 + ky * 5 + kx) * OCC + (ocg << 4)];
                float4 q0 = wp[0], q1 = wp[1], q2 = wp[2], q3 = wp[3];
                float wv[16] = {q0.x, q0.y, q0.z, q0.w, q1.x, q1.y, q1.z, q1.w,
                                q2.x, q2.y, q2.z, q2.w, q3.x, q3.y, q3.z, q3.w};
#pragma unroll
                for (int p = 0; p < 4; p++)
#pragma unroll
                    for (int o = 0; o < 16; o++)
                        acc[p][o] += in[p + kx] * wv[o];
            }
        }
    }

    // Store NHWC
    const int h = by * TILE + py;
#pragma unroll
    for (int p = 0; p < 4; p++) {
        int w = bx * TILE + px + p;
        float4* o4 = (float4*)&g_votes[(((size_t)n * HH + h) * WW + w) * OCH
                                       + ocb + (ocg << 4)];
        o4[0] = make_float4(acc[p][0],  acc[p][1],  acc[p][2],  acc[p][3]);
        o4[1] = make_float4(acc[p][4],  acc[p][5],  acc[p][6],  acc[p][7]);
        o4[2] = make_float4(acc[p][8],  acc[p][9],  acc[p][10], acc[p][11]);
        o4[3] = make_float4(acc[p][12], acc[p][13], acc[p][14], acc[p][15]);
    }
}

// ---------------------------------------------------------------------------
// Routing kernel: one warp per pixel. lane = nc*8+np, v[16] over lp in regs.
// 3 iterations: softmax over NP (shfl 1,2,4), sum over NC (shfl 8,16),
// squash over LP (lane-local), sims += <v, parent>.
// Block = 8 warps = 8 consecutive pixels; output transposed via smem so the
// (B,NP,LP,H,W)-layout store is sector-coalesced.
// ---------------------------------------------------------------------------
__global__ __launch_bounds__(256)
void routing_kernel(float* __restrict__ out) {
    __shared__ float out_s[128][8];

    const int warp = threadIdx.x >> 5;
    const int lane = threadIdx.x & 31;
    const int pixBase = blockIdx.x << 3;          // over B*H*W = 262144, same b per block
    const int pix = pixBase + warp;
    const int b  = pix >> 16;                     // H*W = 65536
    const int hw = pix & 65535;
    const int nc = lane >> 3;
    const int np = lane & 7;

    const float4* vp = (const float4*)
        &g_votes[(((size_t)(b * 4 + nc) << 16) + hw) * OCH + (np << 4)];
    float4 v0 = vp[0], v1 = vp[1], v2 = vp[2], v3 = vp[3];
    float v[16] = {v0.x, v0.y, v0.z, v0.w, v1.x, v1.y, v1.z, v1.w,
                   v2.x, v2.y, v2.z, v2.w, v3.x, v3.y, v3.z, v3.w};

    float sims = 0.f;
    float parent[16];

#pragma unroll
    for (int it = 0; it < 3; it++) {
        // softmax over np (8 lanes sharing nc)
        float m = sims;
        m = fmaxf(m, __shfl_xor_sync(0xffffffffu, m, 1));
        m = fmaxf(m, __shfl_xor_sync(0xffffffffu, m, 2));
        m = fmaxf(m, __shfl_xor_sync(0xffffffffu, m, 4));
        float e = __expf(sims - m);
        float s = e;
        s += __shfl_xor_sync(0xffffffffu, s, 1);
        s += __shfl_xor_sync(0xffffffffu, s, 2);
        s += __shfl_xor_sync(0xffffffffu, s, 4);
        float c = e / s;

        // parent_bs = sum over nc of c*v ; replicated across the 4 nc-lanes
        float sq = 0.f;
#pragma unroll
        for (int l = 0; l < 16; l++) {
            float p = c * v[l];
            p += __shfl_xor_sync(0xffffffffu, p, 8);
            p += __shfl_xor_sync(0xffffffffu, p, 16);
            parent[l] = p;
            sq += p * p;
        }
        // squash over lp
        float norm  = sqrtf(sq);
        float scale = norm / (1.f + sq + 1e-4f);
        float dot = 0.f;
#pragma unroll
        for (int l = 0; l < 16; l++) {
            parent[l] *= scale;
            dot += v[l] * parent[l];
        }
        sims += dot;
    }

    if (nc == 0) {
#pragma unroll
        for (int l = 0; l < 16; l++)
            out_s[(np << 4) + l][warp] = parent[l];
    }
    __syncthreads();

    // Coalesced store: thread t writes 4 floats of channel c at 4 consecutive px
    const int c    = threadIdx.x >> 1;
    const int half = threadIdx.x & 1;
    const int bb   = pixBase >> 16;
    const int hw0  = pixBase & 65535;
    float4 val = make_float4(out_s[c][half * 4 + 0], out_s[c][half * 4 + 1],
                             out_s[c][half * 4 + 2], out_s[c][half * 4 + 3]);
    float4* op = (float4*)&out[((size_t)bb * 128 + c) * 65536 + hw0 + half * 4];
    *op = val;
}

// ---------------------------------------------------------------------------
extern "C" void kernel_launch(void* const* d_in, const int* in_sizes, int n_in,
                              void* d_out, int out_size) {
    const float* x  = (const float*)d_in[0];   // (4,4,16,256,256)
    const float* Wg = (const float*)d_in[1];   // (128,16,5,5)
    float* out = (float*)d_out;                // (4,8,16,256,256)

    const int smem_bytes = (ICH * HALO * HALO + 400 * OCC) * (int)sizeof(float); // 128000
    cudaFuncSetAttribute(conv_votes_kernel,
                         cudaFuncAttributeMaxDynamicSharedMemorySize, smem_bytes);

    conv_votes_kernel<<<16 * 16 * 16 * 2, 256, smem_bytes>>>(x, Wg);
    routing_kernel<<<(4 * 256 * 256) / 8, 256>>>(out);
}

// round 4
// speedup vs baseline: 3.4211x; 3.4147x over previous
#include <cuda_runtime.h>
#include <cuda_bf16.h>
#include <cstdint>

#define HH 256
#define WW 256
#define ICH 16
#define HWSZ (HH * WW)

// votes scratch, NHWC: ((n*H+h)*W+w)*128 + oc   (oc = np*16+lp)
__device__ float g_votes[(size_t)16 * HH * WW * 128];

// ---- conv smem layout (byte offsets into dynamic smem) ----
// Input strips: 132 w-slots, 16 ic bf16 each (32B used), padded to 48B stride
// so fragment LDS (bank = 12*slot + tig) is conflict-free.
#define STRIPB  6336                 // 132 * 48
#define XS_HI   0                    // ring of 6 rows
#define XS_LO   (XS_HI + 6 * STRIPB)   // 38016
#define WF_OFF  (XS_LO + 6 * STRIPB)   // 76032
// W fragment cache: [25 tap][8 ntile][2 hi/lo][32 lane] * 8B = 102400
#define SMEM_TOTAL (WF_OFF + 102400)   // 178432

// ---------------- mma.sync helper (sm_80-era PTX, valid on sm_100) ---------
__device__ __forceinline__ void mma_bf16(float* c, const uint32_t* a,
                                         const uint32_t* b) {
    asm volatile(
        "mma.sync.aligned.m16n8k16.row.col.f32.bf16.bf16.f32 "
        "{%0,%1,%2,%3}, {%4,%5,%6,%7}, {%8,%9}, {%0,%1,%2,%3};"
        : "+f"(c[0]), "+f"(c[1]), "+f"(c[2]), "+f"(c[3])
        : "r"(a[0]), "r"(a[1]), "r"(a[2]), "r"(a[3]), "r"(b[0]), "r"(b[1]));
}

__device__ __forceinline__ void split_bf16(float v, __nv_bfloat16& hi,
                                           __nv_bfloat16& lo) {
    hi = __float2bfloat16(v);
    lo = __float2bfloat16(v - __bfloat162float(hi));
}

// ---------------------------------------------------------------------------
// Conv: grid = 16 n * 2 w_half * 2 oc_half * 8 h_chunks = 512 CTAs, 256 thr.
// CTA computes 32 h-rows; per row D[128 px][64 oc] via 25 taps * 3 split
// passes of m16n8k16 bf16 mma. Warps: wm = warp%4 (32 px), wn = warp/4 (32 oc).
// ---------------------------------------------------------------------------
__global__ __launch_bounds__(256, 1)
void conv_votes_mma(const float* __restrict__ x, const float* __restrict__ Wg) {
    extern __shared__ char smem[];
    const int tid  = threadIdx.x;
    const int warp = tid >> 5, lane = tid & 31;
    const int gid  = lane >> 2, tig = lane & 3;
    const int wm   = warp & 3, wn = warp >> 2;

    const int b  = blockIdx.x;
    const int n  = b & 15;
    const int xh = (b >> 4) & 1;
    const int oh = (b >> 5) & 1;
    const int h0 = (b >> 6) << 5;
    const int wbase = xh << 7;

    const float* xn = x + (size_t)n * ICH * HWSZ;

    // ---- build W fragment cache: entry(tap, ntile, hilo, lane) = 2 regs ----
    // B[k][n] = W[oc = oh*64 + ntile*8 + gid][ic = k];
    // reg0 = {ic 2tig, 2tig+1}, reg1 = {ic 2tig+8, 2tig+9}, hi or lo split.
    for (int e = tid; e < 25 * 8 * 2 * 32; e += 256) {
        int l    = e & 31;
        int hilo = (e >> 5) & 1;
        int nt   = (e >> 6) & 7;
        int tap  = e >> 9;
        int oc   = (oh << 6) + (nt << 3) + (l >> 2);
        int ic0  = (l & 3) << 1;
        const float* wr = Wg + (size_t)oc * 400 + tap;
        __nv_bfloat16 h0a, l0a, h0b, l0b, h1a, l1a, h1b, l1b;
        split_bf16(wr[(ic0    ) * 25], h0a, l0a);
        split_bf16(wr[(ic0 + 1) * 25], h0b, l0b);
        split_bf16(wr[(ic0 + 8) * 25], h1a, l1a);
        split_bf16(wr[(ic0 + 9) * 25], h1b, l1b);
        __nv_bfloat162* dst = (__nv_bfloat162*)(smem + WF_OFF + (size_t)e * 8);
        if (hilo == 0) {
            dst[0] = __nv_bfloat162(h0a, h0b);
            dst[1] = __nv_bfloat162(h1a, h1b);
        } else {
            dst[0] = __nv_bfloat162(l0a, l0b);
            dst[1] = __nv_bfloat162(l1a, l1b);
        }
    }

    // ---- staging helpers (inline, two-phase for latency overlap) ----
    // slot s covers w = wbase - 2 + s, s in [0,132)
    auto stage_direct = [&](int h_in) {
        int slot = ((h_in % 6) + 6) % 6;
        char* bh = smem + XS_HI + slot * STRIPB;
        char* bl = smem + XS_LO + slot * STRIPB;
        bool hok = (h_in >= 0) && (h_in < HH);
        const float* xr = xn + (size_t)(hok ? h_in : 0) * WW;
        for (int i = tid; i < 132 * 16; i += 256) {
            int ic = i >> 7;           // i / 132 approx? careful
            ic = i / 132;
            int s = i - ic * 132;
            int w = wbase - 2 + s;
            float v = 0.f;
            if (hok && (unsigned)w < 256u) v = xr[(size_t)ic * HWSZ + w];
            __nv_bfloat16 hi, lo;
            split_bf16(v, hi, lo);
            *(__nv_bfloat16*)(bh + s * 48 + ic * 2) = hi;
            *(__nv_bfloat16*)(bl + s * 48 + ic * 2) = lo;
        }
    };

    // Prologue: rows h0-2 .. h0+2
    stage_direct(h0 - 2);
    stage_direct(h0 - 1);
    stage_direct(h0);
    stage_direct(h0 + 1);
    stage_direct(h0 + 2);
    __syncthreads();

    float acc[2][4][4];
#pragma unroll
    for (int m = 0; m < 2; m++)
#pragma unroll
        for (int nt = 0; nt < 4; nt++)
#pragma unroll
            for (int r = 0; r < 4; r++) acc[m][nt][r] = 0.f;

    for (int it = 0; it < 32; it++) {
        const int h = h0 + it;

        // Phase 1: issue global loads for row h+3 into registers
        const int hs = h + 3;
        const bool hok = (hs < HH);   // hs >= 0 always here
        float sv[9];
        {
            const float* xr = xn + (size_t)(hok ? hs : 0) * WW;
#pragma unroll
            for (int j = 0; j < 9; j++) {
                int i = tid + j * 256;
                float v = 0.f;
                if (i < 132 * 16) {
                    int ic = i / 132;
                    int s = i - ic * 132;
                    int w = wbase - 2 + s;
                    if (hok && (unsigned)w < 256u) v = xr[(size_t)ic * HWSZ + w];
                }
                sv[j] = v;
            }
        }

        // Phase 2: MMA over 25 taps (covers the LDG latency above)
#pragma unroll 1
        for (int ky = 0; ky < 5; ky++) {
            int slot = (((h - 2 + ky) % 6) + 6) % 6;
            const char* sh = smem + XS_HI + slot * STRIPB;
            const char* sl = smem + XS_LO + slot * STRIPB;
#pragma unroll
            for (int kx = 0; kx < 5; kx++) {
                const int tap = ky * 5 + kx;
                // B fragments (conflict-free LDS.64)
                uint32_t bhf[4][2], blf[4][2];
#pragma unroll
                for (int nt = 0; nt < 4; nt++) {
                    const char* pb = smem + WF_OFF
                        + (((size_t)(tap * 8 + (wn << 2) + nt)) << 9) + lane * 8;
                    uint2 vh = *(const uint2*)pb;
                    uint2 vl = *(const uint2*)(pb + 256);
                    bhf[nt][0] = vh.x; bhf[nt][1] = vh.y;
                    blf[nt][0] = vl.x; blf[nt][1] = vl.y;
                }
                // A fragments (conflict-free LDS.32, 48B stride)
                uint32_t ah[2][4], al[2][4];
#pragma unroll
                for (int m = 0; m < 2; m++) {
                    int s0 = (wm << 5) + (m << 4) + gid + kx;
                    int o0 = s0 * 48 + (tig << 2);
                    int o1 = o0 + 8 * 48;
                    ah[m][0] = *(const uint32_t*)(sh + o0);
                    ah[m][1] = *(const uint32_t*)(sh + o1);
                    ah[m][2] = *(const uint32_t*)(sh + o0 + 16);
                    ah[m][3] = *(const uint32_t*)(sh + o1 + 16);
                    al[m][0] = *(const uint32_t*)(sl + o0);
                    al[m][1] = *(const uint32_t*)(sl + o1);
                    al[m][2] = *(const uint32_t*)(sl + o0 + 16);
                    al[m][3] = *(const uint32_t*)(sl + o1 + 16);
                }
#pragma unroll
                for (int m = 0; m < 2; m++)
#pragma unroll
                    for (int nt = 0; nt < 4; nt++) {
                        mma_bf16(acc[m][nt], ah[m], bhf[nt]);
                        mma_bf16(acc[m][nt], ah[m], blf[nt]);
                        mma_bf16(acc[m][nt], al[m], bhf[nt]);
                    }
            }
        }

        // Phase 3: convert + STS row h+3 (LDGs have landed by now)
        {
            int slot = hs % 6;
            char* bh = smem + XS_HI + slot * STRIPB;
            char* bl = smem + XS_LO + slot * STRIPB;
#pragma unroll
            for (int j = 0; j < 9; j++) {
                int i = tid + j * 256;
                if (i < 132 * 16) {
                    int ic = i / 132;
                    int s = i - ic * 132;
                    __nv_bfloat16 hi, lo;
                    split_bf16(sv[j], hi, lo);
                    *(__nv_bfloat16*)(bh + s * 48 + ic * 2) = hi;
                    *(__nv_bfloat16*)(bl + s * 48 + ic * 2) = lo;
                }
            }
        }

        // Phase 4: epilogue — store D row to g_votes (NHWC), reset acc
        {
            float* vrow = &g_votes[(((size_t)n * HH + h) * WW) * 128];
#pragma unroll
            for (int m = 0; m < 2; m++) {
                int px = wbase + (wm << 5) + (m << 4) + gid;
#pragma unroll
                for (int nt = 0; nt < 4; nt++) {
                    int oc = (oh << 6) + (wn << 5) + (nt << 3) + (tig << 1);
                    float2* p0 = (float2*)&vrow[(size_t)px * 128 + oc];
                    float2* p1 = (float2*)&vrow[(size_t)(px + 8) * 128 + oc];
                    *p0 = make_float2(acc[m][nt][0], acc[m][nt][1]);
                    *p1 = make_float2(acc[m][nt][2], acc[m][nt][3]);
                    acc[m][nt][0] = 0.f; acc[m][nt][1] = 0.f;
                    acc[m][nt][2] = 0.f; acc[m][nt][3] = 0.f;
                }
            }
        }
        __syncthreads();
    }
}

// ---------------------------------------------------------------------------
// Routing (proven): warp per pixel, lane = nc*8+np, lp vector in registers.
// ---------------------------------------------------------------------------
__global__ __launch_bounds__(256)
void routing_kernel(float* __restrict__ out) {
    __shared__ float out_s[128][8];

    const int warp = threadIdx.x >> 5;
    const int lane = threadIdx.x & 31;
    const int pixBase = blockIdx.x << 3;
    const int pix = pixBase + warp;
    const int b = pix >> 16;
    const int hw = pix & 65535;
    const int nc = lane >> 3;
    const int np = lane & 7;

    const float4* vp = (const float4*)
        &g_votes[(((size_t)(b * 4 + nc) << 16) + hw) * 128 + (np << 4)];
    float4 v0 = vp[0], v1 = vp[1], v2 = vp[2], v3 = vp[3];
    float v[16] = {v0.x, v0.y, v0.z, v0.w, v1.x, v1.y, v1.z, v1.w,
                   v2.x, v2.y, v2.z, v2.w, v3.x, v3.y, v3.z, v3.w};

    float sims = 0.f;
    float parent[16];

#pragma unroll
    for (int it = 0; it < 3; it++) {
        float m = sims;
        m = fmaxf(m, __shfl_xor_sync(0xffffffffu, m, 1));
        m = fmaxf(m, __shfl_xor_sync(0xffffffffu, m, 2));
        m = fmaxf(m, __shfl_xor_sync(0xffffffffu, m, 4));
        float e = __expf(sims - m);
        float s = e;
        s += __shfl_xor_sync(0xffffffffu, s, 1);
        s += __shfl_xor_sync(0xffffffffu, s, 2);
        s += __shfl_xor_sync(0xffffffffu, s, 4);
        float c = e / s;

        float sq = 0.f;
#pragma unroll
        for (int l = 0; l < 16; l++) {
            float p = c * v[l];
            p += __shfl_xor_sync(0xffffffffu, p, 8);
            p += __shfl_xor_sync(0xffffffffu, p, 16);
            parent[l] = p;
            sq += p * p;
        }
        float norm = sqrtf(sq);
        float scale = norm / (1.f + sq + 1e-4f);
        float dot = 0.f;
#pragma unroll
        for (int l = 0; l < 16; l++) {
            parent[l] *= scale;
            dot += v[l] * parent[l];
        }
        sims += dot;
    }

    if (nc == 0) {
#pragma unroll
        for (int l = 0; l < 16; l++)
            out_s[(np << 4) + l][warp] = parent[l];
    }
    __syncthreads();

    const int c = threadIdx.x >> 1;
    const int half = threadIdx.x & 1;
    const int bb = pixBase >> 16;
    const int hw0 = pixBase & 65535;
    float4 val = make_float4(out_s[c][half * 4 + 0], out_s[c][half * 4 + 1],
                             out_s[c][half * 4 + 2], out_s[c][half * 4 + 3]);
    float4* op = (float4*)&out[((size_t)bb * 128 + c) * 65536 + hw0 + half * 4];
    *op = val;
}

// ---------------------------------------------------------------------------
extern "C" void kernel_launch(void* const* d_in, const int* in_sizes, int n_in,
                              void* d_out, int out_size) {
    const float* x  = (const float*)d_in[0];   // (4,4,16,256,256)
    const float* Wg = (const float*)d_in[1];   // (128,16,5,5)
    float* out = (float*)d_out;                // (4,8,16,256,256)

    cudaFuncSetAttribute(conv_votes_mma,
                         cudaFuncAttributeMaxDynamicSharedMemorySize, SMEM_TOTAL);
    conv_votes_mma<<<512, 256, SMEM_TOTAL>>>(x, Wg);
    routing_kernel<<<(4 * 256 * 256) / 8, 256>>>(out);
}

// round 5
// speedup vs baseline: 5.2481x; 1.5340x over previous
#include <cuda_runtime.h>
#include <cuda_fp16.h>
#include <cstdint>

#define HH 256
#define WW 256
#define ICH 16
#define HWSZ (HH * WW)

// votes scratch, NHWC: ((n*H+h)*W+w)*128 + oc   (oc = np*16+lp)
__device__ float g_votes[(size_t)16 * HH * WW * 128];

// ---- conv smem layout ----
// Input strips: 260 w-slots (w = slot-2, covers -2..257), 16 ic fp16 = 32B,
// padded to 48B stride (A-fragment LDS conflict-free, proven R4).
#define SLOTS  260
#define STRIPB (SLOTS * 48)          // 12480
#define XS_HI  0                     // 6-row ring, hi strips
#define XS_LO  (6 * STRIPB)          // 74880, lo strips
#define WF_OFF (12 * STRIPB)         // 149760
// W fragment cache: [25 tap][8 ntile][32 lane] * 8B = 51200
#define SMEM_TOTAL (WF_OFF + 51200)  // 200960

__device__ __forceinline__ void mma_f16(float* c, const uint32_t* a,
                                        const uint32_t* b) {
    asm volatile(
        "mma.sync.aligned.m16n8k16.row.col.f32.f16.f16.f32 "
        "{%0,%1,%2,%3}, {%4,%5,%6,%7}, {%8,%9}, {%0,%1,%2,%3};"
        : "+f"(c[0]), "+f"(c[1]), "+f"(c[2]), "+f"(c[3])
        : "r"(a[0]), "r"(a[1]), "r"(a[2]), "r"(a[3]), "r"(b[0]), "r"(b[1]));
}

// ---------------------------------------------------------------------------
// Conv: grid = 16 n * 2 oc_half * 16 h_chunks = 512 CTAs, 256 thr.
// Per h-row: D[256 px][64 oc] via 25 taps * 2 split passes (x hi/lo fp16,
// W single fp16). All 8 warps on M (2 m-tiles each), each warp all 8 n-tiles.
// ---------------------------------------------------------------------------
__global__ __launch_bounds__(256, 1)
void conv_votes_mma(const float* __restrict__ x, const float* __restrict__ Wg) {
    extern __shared__ char smem[];
    const int tid  = threadIdx.x;
    const int warp = tid >> 5, lane = tid & 31;
    const int gid  = lane >> 2, tig = lane & 3;

    const int b  = blockIdx.x;
    const int n  = b & 15;
    const int oh = (b >> 4) & 1;
    const int h0 = (b >> 5) << 4;

    const float* xn = x + (size_t)n * ICH * HWSZ;

    // ---- W fragment cache: entry e = (tap*8+nt)*32 + lane, 8B ----
    // b0 = {W[oc=nt*8+g][ic=2t], [2t+1]}, b1 = {[2t+8], [2t+9]} (fp16)
    for (int e = tid; e < 6400; e += 256) {
        int l = e & 31, nt = (e >> 5) & 7, tap = e >> 8;
        int g = l >> 2, t = l & 3;
        const float* wr = Wg + (size_t)((oh << 6) + nt * 8 + g) * 400 + tap;
        __half2* dst = (__half2*)(smem + WF_OFF + (size_t)e * 8);
        dst[0] = __halves2half2(__float2half(wr[(2 * t) * 25]),
                                __float2half(wr[(2 * t + 1) * 25]));
        dst[1] = __halves2half2(__float2half(wr[(2 * t + 8) * 25]),
                                __float2half(wr[(2 * t + 9) * 25]));
    }

    // ---- zero edge slots {0,1,258,259} of all 12 strips (w pad, never re-written)
    for (int i = tid; i < 12 * 4 * 8; i += 256) {
        int strip = i >> 5;
        int rem = i & 31;
        int sl4 = rem >> 3, f = rem & 7;
        int slot = (sl4 < 2) ? sl4 : (256 + sl4);
        *((float*)(smem + strip * STRIPB + slot * 48) + f) = 0.f;
    }

    // ---- staging: unit j in [0,512): wql=j&3, ic2=(j>>2)&7, wqh=j>>5 ----
    auto sts_unit = [&](const float4& r0, const float4& r1, int ic2, int wq,
                        char* bh, char* bl) {
        const float a0[4] = {r0.x, r0.y, r0.z, r0.w};
        const float a1[4] = {r1.x, r1.y, r1.z, r1.w};
#pragma unroll
        for (int d = 0; d < 4; d++) {
            int slot = wq * 4 + 2 + d;
            __half hh0 = __float2half(a0[d]);
            __half hh1 = __float2half(a1[d]);
            __half ll0 = __float2half(a0[d] - __half2float(hh0));
            __half ll1 = __float2half(a1[d] - __half2float(hh1));
            *(__half2*)(bh + slot * 48 + ic2 * 4) = __halves2half2(hh0, hh1);
            *(__half2*)(bl + slot * 48 + ic2 * 4) = __halves2half2(ll0, ll1);
        }
    };
    auto stage_row = [&](int h_in) {
        const bool hok = (unsigned)h_in < 256u;
        const float* xr = xn + (size_t)(hok ? h_in : 0) * WW;
        int ring = ((h_in % 6) + 6) % 6;
        char* bh = smem + XS_HI + ring * STRIPB;
        char* bl = smem + XS_LO + ring * STRIPB;
#pragma unroll
        for (int u = 0; u < 2; u++) {
            int j = tid + u * 256;
            int wql = j & 3, ic2 = (j >> 2) & 7;
            int wq = (j >> 5) * 4 + wql;
            float4 r0 = make_float4(0.f, 0.f, 0.f, 0.f), r1 = r0;
            if (hok) {
                r0 = *(const float4*)(xr + (size_t)(2 * ic2) * HWSZ + wq * 4);
                r1 = *(const float4*)(xr + (size_t)(2 * ic2 + 1) * HWSZ + wq * 4);
            }
            sts_unit(r0, r1, ic2, wq, bh, bl);
        }
    };

    // Prologue rows h0-2 .. h0+2
    stage_row(h0 - 2);
    stage_row(h0 - 1);
    stage_row(h0);
    stage_row(h0 + 1);
    stage_row(h0 + 2);
    __syncthreads();

    float acc[2][8][4];
#pragma unroll
    for (int m = 0; m < 2; m++)
#pragma unroll
        for (int nt = 0; nt < 8; nt++)
#pragma unroll
            for (int r = 0; r < 4; r++) acc[m][nt][r] = 0.f;

    for (int it = 0; it < 16; it++) {
        const int h = h0 + it;
        const int hs = h + 3;
        const bool hok = hs < 256;

        // Phase 1: prefetch next row's input into registers
        float4 p0[2], p1[2];
        {
            const float* xr = xn + (size_t)(hok ? hs : 0) * WW;
#pragma unroll
            for (int u = 0; u < 2; u++) {
                int j = tid + u * 256;
                int wql = j & 3, ic2 = (j >> 2) & 7;
                int wq = (j >> 5) * 4 + wql;
                p0[u] = make_float4(0.f, 0.f, 0.f, 0.f);
                p1[u] = p0[u];
                if (hok) {
                    p0[u] = *(const float4*)(xr + (size_t)(2 * ic2) * HWSZ + wq * 4);
                    p1[u] = *(const float4*)(xr + (size_t)(2 * ic2 + 1) * HWSZ + wq * 4);
                }
            }
        }

        // Phase 2: MMAs over 25 taps, 2 passes
#pragma unroll 1
        for (int ky = 0; ky < 5; ky++) {
            int ring = ((h - 2 + ky + 6) % 6);
            const char* sh = smem + XS_HI + ring * STRIPB;
            const char* sl = smem + XS_LO + ring * STRIPB;
#pragma unroll
            for (int kx = 0; kx < 5; kx++) {
                const int tap = ky * 5 + kx;
                uint32_t bf[8][2];
#pragma unroll
                for (int nt = 0; nt < 8; nt++) {
                    uint2 vb = *(const uint2*)(smem + WF_OFF
                                               + ((tap * 8 + nt) << 8) + lane * 8);
                    bf[nt][0] = vb.x;
                    bf[nt][1] = vb.y;
                }
                uint32_t ah[2][4], al[2][4];
#pragma unroll
                for (int m = 0; m < 2; m++) {
                    int s0 = (warp * 2 + m) * 16 + gid + kx;
                    int o0 = s0 * 48 + (tig << 2);
                    ah[m][0] = *(const uint32_t*)(sh + o0);
                    ah[m][1] = *(const uint32_t*)(sh + o0 + 384);
                    ah[m][2] = *(const uint32_t*)(sh + o0 + 16);
                    ah[m][3] = *(const uint32_t*)(sh + o0 + 400);
                    al[m][0] = *(const uint32_t*)(sl + o0);
                    al[m][1] = *(const uint32_t*)(sl + o0 + 384);
                    al[m][2] = *(const uint32_t*)(sl + o0 + 16);
                    al[m][3] = *(const uint32_t*)(sl + o0 + 400);
                }
#pragma unroll
                for (int m = 0; m < 2; m++)
#pragma unroll
                    for (int nt = 0; nt < 8; nt++) {
                        mma_f16(acc[m][nt], ah[m], bf[nt]);
                        mma_f16(acc[m][nt], al[m], bf[nt]);
                    }
            }
        }

        // Phase 3: store prefetched row into the ring (slot (h+3)%6, disjoint
        // from h-2..h+2 being read this iteration)
        {
            int ring = hs % 6;
            char* bh = smem + XS_HI + ring * STRIPB;
            char* bl = smem + XS_LO + ring * STRIPB;
#pragma unroll
            for (int u = 0; u < 2; u++) {
                int j = tid + u * 256;
                int wql = j & 3, ic2 = (j >> 2) & 7;
                int wq = (j >> 5) * 4 + wql;
                sts_unit(p0[u], p1[u], ic2, wq, bh, bl);
            }
        }

        // Phase 4: epilogue — D row to g_votes (NHWC)
        {
            float* vrow = &g_votes[(((size_t)n * HH + h) * WW) * 128 + (oh << 6)];
#pragma unroll
            for (int m = 0; m < 2; m++) {
                int px = (warp * 2 + m) * 16 + gid;
#pragma unroll
                for (int nt = 0; nt < 8; nt++) {
                    int oc = (nt << 3) + (tig << 1);
                    *(float2*)&vrow[(size_t)px * 128 + oc] =
                        make_float2(acc[m][nt][0], acc[m][nt][1]);
                    *(float2*)&vrow[(size_t)(px + 8) * 128 + oc] =
                        make_float2(acc[m][nt][2], acc[m][nt][3]);
                    acc[m][nt][0] = 0.f; acc[m][nt][1] = 0.f;
                    acc[m][nt][2] = 0.f; acc[m][nt][3] = 0.f;
                }
            }
        }
        __syncthreads();
    }
}

// ---------------------------------------------------------------------------
// Routing: warp per pixel. lane = lpg*8+np (np bits 0-2, lpg bits 3-4);
// nc lives in REGISTERS (v[4][4]) so the NC-reduction is pure FMA.
// Softmax over np: butterflies masks 1/2/4 (x4 nc). Squash norm + vote dots
// share one 5-value butterfly over masks 8/16. Iter 0: c = 1/8 exactly.
// ---------------------------------------------------------------------------
__global__ __launch_bounds__(256)
void routing_kernel(float* __restrict__ out) {
    __shared__ float out_s[8][132];

    const int tid = threadIdx.x;
    const int warp = tid >> 5, lane = tid & 31;
    const int np = lane & 7, lpg = lane >> 3;
    const int pixBase = blockIdx.x << 3;
    const int pix = pixBase + warp;
    const int b = pix >> 16;
    const int hw = pix & 65535;

    float v[4][4];
#pragma unroll
    for (int nc = 0; nc < 4; nc++) {
        const float4 t = *(const float4*)
            &g_votes[(((size_t)(b * 4 + nc) << 16) + hw) * 128 + np * 16 + lpg * 4];
        v[nc][0] = t.x; v[nc][1] = t.y; v[nc][2] = t.z; v[nc][3] = t.w;
    }

    float sims[4] = {0.f, 0.f, 0.f, 0.f};
    float parent[4];

#pragma unroll
    for (int it = 0; it < 3; it++) {
        float c[4];
        if (it == 0) {
            c[0] = c[1] = c[2] = c[3] = 0.125f;
        } else {
#pragma unroll
            for (int nc = 0; nc < 4; nc++) {
                float m = sims[nc];
                m = fmaxf(m, __shfl_xor_sync(0xffffffffu, m, 1));
                m = fmaxf(m, __shfl_xor_sync(0xffffffffu, m, 2));
                m = fmaxf(m, __shfl_xor_sync(0xffffffffu, m, 4));
                float e = __expf(sims[nc] - m);
                float s = e;
                s += __shfl_xor_sync(0xffffffffu, s, 1);
                s += __shfl_xor_sync(0xffffffffu, s, 2);
                s += __shfl_xor_sync(0xffffffffu, s, 4);
                c[nc] = e / s;
            }
        }
        float pu[4];
#pragma unroll
        for (int j = 0; j < 4; j++)
            pu[j] = c[0] * v[0][j] + c[1] * v[1][j] + c[2] * v[2][j]
                  + c[3] * v[3][j];
        float sq = pu[0] * pu[0] + pu[1] * pu[1] + pu[2] * pu[2] + pu[3] * pu[3];

        if (it < 2) {
            float dp[4];
#pragma unroll
            for (int nc = 0; nc < 4; nc++)
                dp[nc] = v[nc][0] * pu[0] + v[nc][1] * pu[1]
                       + v[nc][2] * pu[2] + v[nc][3] * pu[3];
            sq += __shfl_xor_sync(0xffffffffu, sq, 8);
#pragma unroll
            for (int nc = 0; nc < 4; nc++)
                dp[nc] += __shfl_xor_sync(0xffffffffu, dp[nc], 8);
            sq += __shfl_xor_sync(0xffffffffu, sq, 16);
#pragma unroll
            for (int nc = 0; nc < 4; nc++)
                dp[nc] += __shfl_xor_sync(0xffffffffu, dp[nc], 16);
            float scale = sqrtf(sq) / (1.f + sq + 1e-4f);
#pragma unroll
            for (int nc = 0; nc < 4; nc++) sims[nc] += scale * dp[nc];
        } else {
            sq += __shfl_xor_sync(0xffffffffu, sq, 8);
            sq += __shfl_xor_sync(0xffffffffu, sq, 16);
            float scale = sqrtf(sq) / (1.f + sq + 1e-4f);
#pragma unroll
            for (int j = 0; j < 4; j++) parent[j] = scale * pu[j];
        }
    }

    *(float4*)&out_s[warp][np * 16 + lpg * 4] =
        make_float4(parent[0], parent[1], parent[2], parent[3]);
    __syncthreads();

    // Transposed store: thread -> (channel, 4 px)
    const int ch = tid >> 1, half = tid & 1;
    float4 val = make_float4(out_s[half * 4 + 0][ch], out_s[half * 4 + 1][ch],
                             out_s[half * 4 + 2][ch], out_s[half * 4 + 3][ch]);
    *(float4*)&out[((size_t)(pixBase >> 16) * 128 + ch) * 65536
                   + (pixBase & 65535) + half * 4] = val;
}

// ---------------------------------------------------------------------------
extern "C" void kernel_launch(void* const* d_in, const int* in_sizes, int n_in,
                              void* d_out, int out_size) {
    const float* x  = (const float*)d_in[0];   // (4,4,16,256,256)
    const float* Wg = (const float*)d_in[1];   // (128,16,5,5)
    float* out = (float*)d_out;                // (4,8,16,256,256)

    cudaFuncSetAttribute(conv_votes_mma,
                         cudaFuncAttributeMaxDynamicSharedMemorySize, SMEM_TOTAL);
    conv_votes_mma<<<512, 256, SMEM_TOTAL>>>(x, Wg);
    routing_kernel<<<(4 * 256 * 256) / 8, 256>>>(out);
}